// round 1
// baseline (speedup 1.0000x reference)
#include <cuda_runtime.h>
#include <math.h>

#define Bn   8
#define Cn   256
#define Hn   64
#define Wn   64
#define Pn   4096            // Hn*Wn
#define NHn  8
#define HDn  32
#define SCALEF 0.1767766952966369f   // 1/sqrt(32)

// Scratch: qkv in head-blocked pixel-major layout [b][g=s*8+hd][p][d], d contiguous
__device__ float g_qkv[(size_t)Bn * 3 * NHn * Pn * HDn];   // ~100.7 MB
// Attention output channel-major [b][c][p] (same layout as x) for proj GEMM
__device__ float g_attn[(size_t)Bn * Cn * Pn];             // ~33.5 MB

// ---------------------------------------------------------------------------
// GEMM: Out[b][o][p] = sum_c Wm[o][c] * Xin[b][c][p] + bias[o]
// Tile 64(M) x 64(N) x 16(K), 256 threads, 4x4 accum per thread, float4 I/O.
// BLOCKED=true  : M=768, writes g_qkv blocked layout [(b*24+o>>5)][p][o&31]
// BLOCKED=false : M=256, writes plain [b][o][p]
// ---------------------------------------------------------------------------
template <bool BLOCKED>
__global__ void gemm_kernel(const float* __restrict__ Wm,
                            const float* __restrict__ Xin,
                            const float* __restrict__ bias,
                            float* __restrict__ Out) {
    __shared__ float As[16][64];   // [k][m]
    __shared__ float Bs[16][64];   // [k][n]

    const int t  = threadIdx.x;
    const int tm = t >> 4;         // 0..15
    const int tn = t & 15;         // 0..15
    const int b  = blockIdx.z;
    const int m0 = blockIdx.y * 64;
    const int n0 = blockIdx.x * 64;

    const float* Xb = Xin + (size_t)b * Cn * Pn;

    // staging indices
    const int a_row = t >> 2;          // 0..63 (m within tile)
    const int a_col = (t & 3) * 4;     // 0..12 (k within tile)

    float acc[4][4] = {};

    for (int k0 = 0; k0 < Cn; k0 += 16) {
        float4 av = *(const float4*)(Wm + (size_t)(m0 + a_row) * Cn + k0 + a_col);
        float4 bv = *(const float4*)(Xb + (size_t)(k0 + tm) * Pn + n0 + tn * 4);
        __syncthreads();
        As[a_col + 0][a_row] = av.x;
        As[a_col + 1][a_row] = av.y;
        As[a_col + 2][a_row] = av.z;
        As[a_col + 3][a_row] = av.w;
        *(float4*)&Bs[tm][tn * 4] = bv;
        __syncthreads();
#pragma unroll
        for (int kk = 0; kk < 16; kk++) {
            float4 a = *(const float4*)&As[kk][tm * 4];
            float4 x = *(const float4*)&Bs[kk][tn * 4];
            acc[0][0] += a.x * x.x; acc[0][1] += a.x * x.y; acc[0][2] += a.x * x.z; acc[0][3] += a.x * x.w;
            acc[1][0] += a.y * x.x; acc[1][1] += a.y * x.y; acc[1][2] += a.y * x.z; acc[1][3] += a.y * x.w;
            acc[2][0] += a.z * x.x; acc[2][1] += a.z * x.y; acc[2][2] += a.z * x.z; acc[2][3] += a.z * x.w;
            acc[3][0] += a.w * x.x; acc[3][1] += a.w * x.y; acc[3][2] += a.w * x.z; acc[3][3] += a.w * x.w;
        }
    }

    if (BLOCKED) {
        // o = m0 + tm*4 + i  (4 consecutive o's, never cross a 32 boundary)
        const int mb = m0 + tm * 4;
        const int g  = mb >> 5;        // 0..23
        const int d0 = mb & 31;
        const float bx = bias[mb], by = bias[mb + 1], bz = bias[mb + 2], bw = bias[mb + 3];
        float* obase = Out + ((size_t)(b * 24 + g) * Pn) * HDn + d0;
#pragma unroll
        for (int j = 0; j < 4; j++) {
            const int p = n0 + tn * 4 + j;
            float4 v = make_float4(acc[0][j] + bx, acc[1][j] + by,
                                   acc[2][j] + bz, acc[3][j] + bw);
            *(float4*)(obase + (size_t)p * HDn) = v;
        }
    } else {
        const int nb = n0 + tn * 4;
#pragma unroll
        for (int i = 0; i < 4; i++) {
            const int m = m0 + tm * 4 + i;
            const float bo = bias[m];
            float4 v = make_float4(acc[i][0] + bo, acc[i][1] + bo,
                                   acc[i][2] + bo, acc[i][3] + bo);
            *(float4*)(Out + ((size_t)b * 256 + m) * Pn + nb) = v;
        }
    }
}

// ---------------------------------------------------------------------------
// Attention: one thread per (b, head, pixel). q/k/v read as contiguous float4
// vectors from the blocked qkv layout. 9-neighbor dilated 3x3, softmax over 9
// (zero score / zero v for out-of-bounds, matching zero-padded reference).
// Output written channel-major to g_attn.
// ---------------------------------------------------------------------------
__global__ void attn_kernel() {
    const int bh = blockIdx.y;              // b*8 + hd
    const int b  = bh >> 3;
    const int hd = bh & 7;
    const int p  = blockIdx.x * blockDim.x + threadIdx.x;   // 0..4095
    const int h  = p >> 6;
    const int w  = p & 63;
    const int dil = (hd & 3) + 1;

    const float* qb = g_qkv + ((size_t)(b * 24 + 0 * 8 + hd)) * Pn * HDn;
    const float* kb = g_qkv + ((size_t)(b * 24 + 1 * 8 + hd)) * Pn * HDn;
    const float* vb = g_qkv + ((size_t)(b * 24 + 2 * 8 + hd)) * Pn * HDn;

    float4 q[8];
#pragma unroll
    for (int i = 0; i < 8; i++) q[i] = *(const float4*)(qb + (size_t)p * HDn + i * 4);

    float s[9];
    int   np[9];
#pragma unroll
    for (int dy = 0; dy < 3; dy++) {
#pragma unroll
        for (int dx = 0; dx < 3; dx++) {
            const int j  = dy * 3 + dx;
            const int hh = h + (dy - 1) * dil;
            const int ww = w + (dx - 1) * dil;
            if (hh >= 0 && hh < Hn && ww >= 0 && ww < Wn) {
                const int pn = hh * Wn + ww;
                np[j] = pn;
                const float* kp = kb + (size_t)pn * HDn;
                float acc = 0.f;
#pragma unroll
                for (int i = 0; i < 8; i++) {
                    float4 k4 = *(const float4*)(kp + i * 4);
                    acc += q[i].x * k4.x + q[i].y * k4.y + q[i].z * k4.z + q[i].w * k4.w;
                }
                s[j] = acc * SCALEF;
            } else {
                np[j] = -1;
                s[j]  = 0.f;   // zero-padded k => score 0 (still in softmax)
            }
        }
    }

    float mx = s[0];
#pragma unroll
    for (int j = 1; j < 9; j++) mx = fmaxf(mx, s[j]);
    float e[9];
    float sum = 0.f;
#pragma unroll
    for (int j = 0; j < 9; j++) { e[j] = expf(s[j] - mx); sum += e[j]; }
    const float inv = 1.f / sum;
#pragma unroll
    for (int j = 0; j < 9; j++) e[j] *= inv;

    float* ob = g_attn + ((size_t)b * Cn + hd * HDn) * Pn;
#pragma unroll
    for (int i = 0; i < 8; i++) {
        float ox = 0.f, oy = 0.f, oz = 0.f, ow = 0.f;
#pragma unroll
        for (int j = 0; j < 9; j++) {
            if (np[j] >= 0) {   // OOB v is zero-padded: contributes nothing
                float4 v4 = *(const float4*)(vb + (size_t)np[j] * HDn + i * 4);
                ox += e[j] * v4.x; oy += e[j] * v4.y;
                oz += e[j] * v4.z; ow += e[j] * v4.w;
            }
        }
        // channel-major store: c = hd*32 + i*4 + l  (coalesced across warp in p)
        ob[(size_t)(i * 4 + 0) * Pn + p] = ox;
        ob[(size_t)(i * 4 + 1) * Pn + p] = oy;
        ob[(size_t)(i * 4 + 2) * Pn + p] = oz;
        ob[(size_t)(i * 4 + 3) * Pn + p] = ow;
    }
}

// ---------------------------------------------------------------------------
extern "C" void kernel_launch(void* const* d_in, const int* in_sizes, int n_in,
                              void* d_out, int out_size) {
    const float* x      = (const float*)d_in[0];
    const float* w_qkv  = (const float*)d_in[1];
    const float* b_qkv  = (const float*)d_in[2];
    const float* w_proj = (const float*)d_in[3];
    const float* b_proj = (const float*)d_in[4];
    float* out = (float*)d_out;

    float *qkv_ptr = nullptr, *attn_ptr = nullptr;
    cudaGetSymbolAddress((void**)&qkv_ptr,  g_qkv);
    cudaGetSymbolAddress((void**)&attn_ptr, g_attn);

    // K1: QKV GEMM (M=768) -> blocked layout scratch
    gemm_kernel<true><<<dim3(Pn / 64, 768 / 64, Bn), 256>>>(w_qkv, x, b_qkv, qkv_ptr);
    // K2: dilated local attention
    attn_kernel<<<dim3(Pn / 128, Bn * NHn), 128>>>();
    // K3: output projection (M=256) -> d_out
    gemm_kernel<false><<<dim3(Pn / 64, 256 / 64, Bn), 256>>>(w_proj, attn_ptr, b_proj, out);
}

// round 2
// speedup vs baseline: 1.4622x; 1.4622x over previous
#include <cuda_runtime.h>
#include <math.h>

#define Bn   8
#define Cn   256
#define Hn   64
#define Wn   64
#define Pn   4096            // Hn*Wn
#define NHn  8
#define HDn  32
#define SCALEF 0.1767766952966369f   // 1/sqrt(32)

// qkv scratch, quad-interleaved: [b][g=s*8+hd : 24][dq:8][p:4096][4]
// element (b,g,d,p) at ((b*24+g)*8 + d/4)*Pn*4 + p*4 + (d%4)
__device__ float g_qkv[(size_t)Bn * 3 * NHn * Pn * HDn];   // ~100.7 MB
// Attention output channel-major [b][c][p] for proj GEMM
__device__ float g_attn[(size_t)Bn * Cn * Pn];             // ~33.5 MB

// ---------------------------------------------------------------------------
// GEMM: Out[b][o][p] = sum_c Wm[o][c] * Xin[b][c][p] + bias[o]
// 128(M) x 128(N) x 8(K) tile, 256 threads, 8x8 microtile, double-buffered.
// BLOCKED=true : M=768, writes g_qkv quad-interleaved layout
// BLOCKED=false: M=256, writes plain [b][o][p]
// ---------------------------------------------------------------------------
template <bool BLOCKED>
__global__ void __launch_bounds__(256) gemm_kernel(const float* __restrict__ Wm,
                            const float* __restrict__ Xin,
                            const float* __restrict__ bias,
                            float* __restrict__ Out) {
    __shared__ float As[2][8][128];   // [buf][k][m]
    __shared__ float Bs[2][8][128];   // [buf][k][n]

    const int t  = threadIdx.x;
    const int b  = blockIdx.z;
    const int m0 = blockIdx.y * 128;
    const int n0 = blockIdx.x * 128;

    // staging indices
    const int a_row  = t >> 1;          // 0..127  (m)
    const int a_quad = (t & 1) * 4;     // 0 or 4  (k)
    const int b_row  = t >> 5;          // 0..7    (k)
    const int b_col  = (t & 31) * 4;    // 0..124  (n)

    // compute indices
    const int tx = t & 15;              // n
    const int ty = t >> 4;              // m

    const float* Aptr = Wm + (size_t)(m0 + a_row) * Cn + a_quad;
    const float* Bptr = Xin + (size_t)b * Cn * Pn + (size_t)b_row * Pn + n0 + b_col;

    // load first tile
    float4 av = *(const float4*)Aptr;
    float4 bv = *(const float4*)Bptr;
    As[0][a_quad + 0][a_row] = av.x;
    As[0][a_quad + 1][a_row] = av.y;
    As[0][a_quad + 2][a_row] = av.z;
    As[0][a_quad + 3][a_row] = av.w;
    *(float4*)&Bs[0][b_row][b_col] = bv;
    __syncthreads();

    float acc[8][8] = {};
    int buf = 0;

    for (int k0 = 0; k0 < Cn; k0 += 8) {
        const bool has_next = (k0 + 8 < Cn);
        float4 avn, bvn;
        if (has_next) {
            avn = *(const float4*)(Aptr + k0 + 8);
            bvn = *(const float4*)(Bptr + (size_t)(k0 + 8) * Pn);
        }
#pragma unroll
        for (int kk = 0; kk < 8; kk++) {
            float4 a0 = *(const float4*)&As[buf][kk][ty * 4];
            float4 a1 = *(const float4*)&As[buf][kk][ty * 4 + 64];
            float4 b0 = *(const float4*)&Bs[buf][kk][tx * 4];
            float4 b1 = *(const float4*)&Bs[buf][kk][tx * 4 + 64];
            float ar[8] = {a0.x, a0.y, a0.z, a0.w, a1.x, a1.y, a1.z, a1.w};
            float br[8] = {b0.x, b0.y, b0.z, b0.w, b1.x, b1.y, b1.z, b1.w};
#pragma unroll
            for (int i = 0; i < 8; i++)
#pragma unroll
                for (int j = 0; j < 8; j++)
                    acc[i][j] += ar[i] * br[j];
        }
        if (has_next) {
            As[buf ^ 1][a_quad + 0][a_row] = avn.x;
            As[buf ^ 1][a_quad + 1][a_row] = avn.y;
            As[buf ^ 1][a_quad + 2][a_row] = avn.z;
            As[buf ^ 1][a_quad + 3][a_row] = avn.w;
            *(float4*)&Bs[buf ^ 1][b_row][b_col] = bvn;
            __syncthreads();
            buf ^= 1;
        }
    }

    if (BLOCKED) {
        // 4 consecutive output channels per row-half = exactly one d-quad
#pragma unroll
        for (int rh = 0; rh < 2; rh++) {
            const int m  = m0 + ty * 4 + rh * 64;
            const int g  = m >> 5;
            const int dq = (m & 31) >> 2;
            const float b0v = bias[m], b1v = bias[m + 1], b2v = bias[m + 2], b3v = bias[m + 3];
            float* obase = Out + (((size_t)(b * 24 + g) * 8 + dq) * Pn) * 4;
#pragma unroll
            for (int ch = 0; ch < 2; ch++) {
#pragma unroll
                for (int j = 0; j < 4; j++) {
                    const int p = n0 + tx * 4 + ch * 64 + j;
                    float4 v = make_float4(acc[rh * 4 + 0][ch * 4 + j] + b0v,
                                           acc[rh * 4 + 1][ch * 4 + j] + b1v,
                                           acc[rh * 4 + 2][ch * 4 + j] + b2v,
                                           acc[rh * 4 + 3][ch * 4 + j] + b3v);
                    *(float4*)(obase + (size_t)p * 4) = v;
                }
            }
        }
    } else {
#pragma unroll
        for (int rh = 0; rh < 2; rh++) {
#pragma unroll
            for (int i = 0; i < 4; i++) {
                const int m = m0 + ty * 4 + rh * 64 + i;
                const float bo = bias[m];
                float* orow = Out + ((size_t)b * 256 + m) * Pn + n0;
#pragma unroll
                for (int ch = 0; ch < 2; ch++) {
                    float4 v = make_float4(acc[rh * 4 + i][ch * 4 + 0] + bo,
                                           acc[rh * 4 + i][ch * 4 + 1] + bo,
                                           acc[rh * 4 + i][ch * 4 + 2] + bo,
                                           acc[rh * 4 + i][ch * 4 + 3] + bo);
                    *(float4*)(orow + tx * 4 + ch * 64) = v;
                }
            }
        }
    }
}

// ---------------------------------------------------------------------------
// Attention: one thread per (b, head, pixel). With the quad-interleaved qkv
// layout, every load for a fixed (neighbor j, quad i) is contiguous float4
// across lanes (p contiguous) -> fully coalesced.
// ---------------------------------------------------------------------------
__global__ void attn_kernel() {
    const int bh = blockIdx.y;              // b*8 + hd
    const int b  = bh >> 3;
    const int hd = bh & 7;
    const int p  = blockIdx.x * blockDim.x + threadIdx.x;   // 0..4095
    const int h  = p >> 6;
    const int w  = p & 63;
    const int dil = (hd & 3) + 1;

    const float* qb = g_qkv + ((size_t)((b * 24 + 0 * 8 + hd) * 8)) * Pn * 4;
    const float* kb = g_qkv + ((size_t)((b * 24 + 1 * 8 + hd) * 8)) * Pn * 4;
    const float* vb = g_qkv + ((size_t)((b * 24 + 2 * 8 + hd) * 8)) * Pn * 4;

    float4 q[8];
#pragma unroll
    for (int i = 0; i < 8; i++)
        q[i] = *(const float4*)(qb + ((size_t)i * Pn + p) * 4);

    float s[9];
    int   np[9];
#pragma unroll
    for (int dy = 0; dy < 3; dy++) {
#pragma unroll
        for (int dx = 0; dx < 3; dx++) {
            const int j  = dy * 3 + dx;
            const int hh = h + (dy - 1) * dil;
            const int ww = w + (dx - 1) * dil;
            if (hh >= 0 && hh < Hn && ww >= 0 && ww < Wn) {
                const int pn = hh * Wn + ww;
                np[j] = pn;
                float acc = 0.f;
#pragma unroll
                for (int i = 0; i < 8; i++) {
                    float4 k4 = *(const float4*)(kb + ((size_t)i * Pn + pn) * 4);
                    acc += q[i].x * k4.x + q[i].y * k4.y + q[i].z * k4.z + q[i].w * k4.w;
                }
                s[j] = acc * SCALEF;
            } else {
                np[j] = -1;
                s[j]  = 0.f;   // zero-padded k => score 0 (still in softmax)
            }
        }
    }

    float mx = s[0];
#pragma unroll
    for (int j = 1; j < 9; j++) mx = fmaxf(mx, s[j]);
    float e[9];
    float sum = 0.f;
#pragma unroll
    for (int j = 0; j < 9; j++) { e[j] = __expf(s[j] - mx); sum += e[j]; }
    const float inv = 1.f / sum;
#pragma unroll
    for (int j = 0; j < 9; j++) e[j] *= inv;

    float* ob = g_attn + ((size_t)b * Cn + hd * HDn) * Pn;
#pragma unroll
    for (int i = 0; i < 8; i++) {
        float ox = 0.f, oy = 0.f, oz = 0.f, ow = 0.f;
#pragma unroll
        for (int j = 0; j < 9; j++) {
            if (np[j] >= 0) {   // OOB v is zero-padded: contributes nothing
                float4 v4 = *(const float4*)(vb + ((size_t)i * Pn + np[j]) * 4);
                ox += e[j] * v4.x; oy += e[j] * v4.y;
                oz += e[j] * v4.z; ow += e[j] * v4.w;
            }
        }
        // channel-major store: c = hd*32 + i*4 + l  (coalesced across warp in p)
        ob[(size_t)(i * 4 + 0) * Pn + p] = ox;
        ob[(size_t)(i * 4 + 1) * Pn + p] = oy;
        ob[(size_t)(i * 4 + 2) * Pn + p] = oz;
        ob[(size_t)(i * 4 + 3) * Pn + p] = ow;
    }
}

// ---------------------------------------------------------------------------
extern "C" void kernel_launch(void* const* d_in, const int* in_sizes, int n_in,
                              void* d_out, int out_size) {
    const float* x      = (const float*)d_in[0];
    const float* w_qkv  = (const float*)d_in[1];
    const float* b_qkv  = (const float*)d_in[2];
    const float* w_proj = (const float*)d_in[3];
    const float* b_proj = (const float*)d_in[4];
    float* out = (float*)d_out;

    float *qkv_ptr = nullptr, *attn_ptr = nullptr;
    cudaGetSymbolAddress((void**)&qkv_ptr,  g_qkv);
    cudaGetSymbolAddress((void**)&attn_ptr, g_attn);

    // K1: QKV GEMM (M=768) -> quad-interleaved scratch
    gemm_kernel<true><<<dim3(Pn / 128, 768 / 128, Bn), 256>>>(w_qkv, x, b_qkv, qkv_ptr);
    // K2: dilated local attention
    attn_kernel<<<dim3(Pn / 128, Bn * NHn), 128>>>();
    // K3: output projection (M=256) -> d_out
    gemm_kernel<false><<<dim3(Pn / 128, 256 / 128, Bn), 256>>>(w_proj, attn_ptr, b_proj, out);
}

// round 4
// speedup vs baseline: 2.8194x; 1.9282x over previous
#include <cuda_runtime.h>
#include <cuda_bf16.h>
#include <stdint.h>
#include <math.h>

#define Bn   8
#define Cn   256
#define Hn   64
#define Wn   64
#define Pn   4096
#define SCALEF 0.1767766952966369f

// qkv quad-interleaved: [b][g=s*8+hd :24][dq:8][p:4096][4] fp32
__device__ float g_qkv[(size_t)Bn * 24 * Pn * 32];
__device__ __nv_bfloat16 g_w1[768 * 768];              // [Whi|Wlo|Whi] along K
__device__ __nv_bfloat16 g_w2[256 * 768];
__device__ __nv_bfloat16 g_xhi[(size_t)Bn * Pn * Cn];  // [b][p][c]
__device__ __nv_bfloat16 g_xlo[(size_t)Bn * Pn * Cn];
__device__ __nv_bfloat16 g_ahi[(size_t)Bn * Pn * Cn];
__device__ __nv_bfloat16 g_alo[(size_t)Bn * Pn * Cn];

// ---------------- helpers (baseline PTX only: sm_80-level features) ----------------
__device__ __forceinline__ uint32_t s2u(const void* p) {
    uint32_t a;
    asm("{ .reg .u64 t; cvta.to.shared.u64 t, %1; cvt.u32.u64 %0, t; }" : "=r"(a) : "l"(p));
    return a;
}
__device__ __forceinline__ void cp16(uint32_t dst, const void* src) {
    asm volatile("cp.async.cg.shared.global [%0], [%1], 16;" :: "r"(dst), "l"(src));
}
#define CP_COMMIT() asm volatile("cp.async.commit_group;" ::: "memory")
#define CP_WAIT1()  asm volatile("cp.async.wait_group 1;" ::: "memory")
#define SWZ(o) ((o) ^ (((o) >> 3) & 0x70))

__device__ __forceinline__ void ldsm4(uint32_t* r, uint32_t a) {
    asm volatile("ldmatrix.sync.aligned.m8n8.x4.shared.b16 {%0,%1,%2,%3}, [%4];"
                 : "=r"(r[0]), "=r"(r[1]), "=r"(r[2]), "=r"(r[3]) : "r"(a));
}
__device__ __forceinline__ void mma16816(float* c, const uint32_t* a, uint32_t b0, uint32_t b1) {
    asm volatile("mma.sync.aligned.m16n8k16.row.col.f32.bf16.bf16.f32 "
                 "{%0,%1,%2,%3},{%4,%5,%6,%7},{%8,%9},{%0,%1,%2,%3};"
                 : "+f"(c[0]), "+f"(c[1]), "+f"(c[2]), "+f"(c[3])
                 : "r"(a[0]), "r"(a[1]), "r"(a[2]), "r"(a[3]), "r"(b0), "r"(b1));
}

// ---------------- prep: weight hi/lo concat ----------------
__global__ void prep_w(const float* __restrict__ wq, const float* __restrict__ wp) {
    int idx = blockIdx.x * 256 + threadIdx.x;
    const int tot1 = 768 * 768;
    if (idx < tot1) {
        int m = idx / 768, k = idx % 768;
        float v = (k < 256) ? wq[m * 256 + k] : (k < 512 ? wq[m * 256 + k - 256] : wq[m * 256 + k - 512]);
        __nv_bfloat16 h = __float2bfloat16(v);
        if (k >= 256 && k < 512) h = __float2bfloat16(v - __bfloat162float(__float2bfloat16(v)));
        g_w1[idx] = h;
    }
    int idx2 = idx - tot1;
    if (idx2 >= 0 && idx2 < 256 * 768) {
        int m = idx2 / 768, k = idx2 % 768;
        float v = (k < 256) ? wp[m * 256 + k] : (k < 512 ? wp[m * 256 + k - 256] : wp[m * 256 + k - 512]);
        __nv_bfloat16 h = __float2bfloat16(v);
        if (k >= 256 && k < 512) h = __float2bfloat16(v - __bfloat162float(__float2bfloat16(v)));
        g_w2[idx2] = h;
    }
}

// -------- transpose + hi/lo split: [b][c][p] fp32 -> [b][p][c] bf16 x2 --------
__global__ void conv_split(const float* __restrict__ in,
                           __nv_bfloat16* __restrict__ ohi,
                           __nv_bfloat16* __restrict__ olo) {
    __shared__ float t[32][33];
    const int b = blockIdx.z, c0 = blockIdx.y * 32, p0 = blockIdx.x * 32;
    const int tx = threadIdx.x, ty = threadIdx.y;
    const float* ip = in + ((size_t)b * Cn + c0) * Pn + p0;
#pragma unroll
    for (int r = 0; r < 4; r++)
        t[ty + r * 8][tx] = ip[(size_t)(ty + r * 8) * Pn + tx];
    __syncthreads();
#pragma unroll
    for (int r = 0; r < 4; r++) {
        int pr = ty + r * 8;
        float v = t[tx][pr];
        __nv_bfloat16 h = __float2bfloat16(v);
        __nv_bfloat16 l = __float2bfloat16(v - __bfloat162float(h));
        size_t o = ((size_t)b * Pn + p0 + pr) * Cn + c0 + tx;
        ohi[o] = h; olo[o] = l;
    }
}

// ---------------- HMMA bf16 GEMM: D[m][n] = sum_k A[m][k]*Bmat[n][k] + bias[m] ----------------
// A: [M][768] bf16.  Bmat rows = pixels, 256-wide chunks from hi/lo arrays (3-term split).
// 128x128 CTA tile, 8 warps 2(M)x4(N), warp tile 64x32, 3-stage cp.async pipeline.
// LAYOUT 0: quad-interleaved qkv output. LAYOUT 1: [b][m][p] fp32 (final out).
template <int LAYOUT>
__global__ void __launch_bounds__(256) hmma_gemm(const __nv_bfloat16* __restrict__ A,
                                                 const __nv_bfloat16* __restrict__ Bhi,
                                                 const __nv_bfloat16* __restrict__ Blo,
                                                 const float* __restrict__ bias,
                                                 float* __restrict__ Out) {
    extern __shared__ char smraw[];
    const uint32_t sbr = s2u(smraw);
    const uint32_t sb = (sbr + 1023u) & ~1023u;
    char* smg = smraw + (sb - sbr);

    const int t = threadIdx.x, lane = t & 31, wid = t >> 5;
    const int b = blockIdx.z, m0 = blockIdx.y * 128, n0 = blockIdx.x * 128;
    const int wm = wid >> 2, wn = wid & 3;

    const uint32_t sA = sb;              // 3 x 16KB A stage buffers
    const uint32_t sB = sb + 49152;      // 3 x 16KB B stage buffers

    auto load_stage = [&](int c, int buf) {
        const __nv_bfloat16* asrc = A + (size_t)m0 * 768 + c * 64;
        const __nv_bfloat16* bsrc = ((c < 8) ? Bhi : Blo) + ((size_t)(b * Pn + n0)) * 256 + (c & 3) * 64;
        const uint32_t ab = sA + buf * 16384, bb = sB + buf * 16384;
#pragma unroll
        for (int i = 0; i < 4; i++) {
            int u = t + i * 256, row = u >> 3, ch = u & 7;
            uint32_t off = row * 128 + ch * 16;
            uint32_t sw = SWZ(off);
            cp16(ab + sw, asrc + (size_t)row * 768 + ch * 8);
            cp16(bb + sw, bsrc + (size_t)row * 256 + ch * 8);
        }
    };

    float acc[4][4][4] = {};

    load_stage(0, 0); CP_COMMIT();
    load_stage(1, 1); CP_COMMIT();

    for (int c = 0; c < 12; c++) {
        const int buf = c % 3;
        CP_WAIT1();
        __syncthreads();
        const uint32_t abase = sA + buf * 16384, bbase = sB + buf * 16384;
#pragma unroll
        for (int kk = 0; kk < 4; kk++) {
            uint32_t af[4][4], bf[2][4];
#pragma unroll
            for (int mf = 0; mf < 4; mf++) {
                uint32_t off = (uint32_t)(wm * 64 + mf * 16 + (lane & 15)) * 128
                             + kk * 32 + ((lane >> 4) << 4);
                ldsm4(af[mf], abase + SWZ(off));
            }
#pragma unroll
            for (int np = 0; np < 2; np++) {
                uint32_t off = (uint32_t)(wn * 32 + np * 16 + (lane & 7) + ((lane >> 4) << 3)) * 128
                             + kk * 32 + (((lane >> 3) & 1) << 4);
                ldsm4(bf[np], bbase + SWZ(off));
            }
#pragma unroll
            for (int mf = 0; mf < 4; mf++)
#pragma unroll
                for (int nf = 0; nf < 4; nf++)
                    mma16816(acc[mf][nf], af[mf], bf[nf >> 1][(nf & 1) * 2], bf[nf >> 1][(nf & 1) * 2 + 1]);
        }
        if (c + 2 < 12) { load_stage(c + 2, (c + 2) % 3); CP_COMMIT(); }
    }

    if (LAYOUT == 0) {
        __syncthreads();                       // tile bufs being reused as epilogue patch
        float* patch = (float*)smg + wid * (64 * 33);
#pragma unroll
        for (int mf = 0; mf < 4; mf++) {
            const int r0 = mf * 16 + (lane >> 2);
#pragma unroll
            for (int nf = 0; nf < 4; nf++) {
                const int cb = nf * 8 + 2 * (lane & 3);
                patch[r0 * 33 + cb]           = acc[mf][nf][0];
                patch[r0 * 33 + cb + 1]       = acc[mf][nf][1];
                patch[(r0 + 8) * 33 + cb]     = acc[mf][nf][2];
                patch[(r0 + 8) * 33 + cb + 1] = acc[mf][nf][3];
            }
        }
        __syncwarp();
        const int p = n0 + wn * 32 + lane;
#pragma unroll
        for (int q = 0; q < 16; q++) {
            const int mg = m0 + wm * 64 + q * 4;
            float4 v = make_float4(patch[(q * 4 + 0) * 33 + lane] + bias[mg],
                                   patch[(q * 4 + 1) * 33 + lane] + bias[mg + 1],
                                   patch[(q * 4 + 2) * 33 + lane] + bias[mg + 2],
                                   patch[(q * 4 + 3) * 33 + lane] + bias[mg + 3]);
            const int g = mg >> 5, dq = (mg & 31) >> 2;
            *(float4*)(Out + (((size_t)(b * 24 + g) * 8 + dq) * Pn + p) * 4) = v;
        }
    } else {
#pragma unroll
        for (int mf = 0; mf < 4; mf++) {
            const int r0 = m0 + wm * 64 + mf * 16 + (lane >> 2);
            const float b0v = bias[r0], b1v = bias[r0 + 8];
#pragma unroll
            for (int nf = 0; nf < 4; nf++) {
                const int cc = n0 + wn * 32 + nf * 8 + 2 * (lane & 3);
                float2 v0 = make_float2(acc[mf][nf][0] + b0v, acc[mf][nf][1] + b0v);
                *(float2*)(Out + ((size_t)b * 256 + r0) * Pn + cc) = v0;
                float2 v1 = make_float2(acc[mf][nf][2] + b1v, acc[mf][nf][3] + b1v);
                *(float2*)(Out + ((size_t)b * 256 + r0 + 8) * Pn + cc) = v1;
            }
        }
    }
}

// ---------------- attention: reads fp32 quad qkv, writes bf16 hi/lo [b][p][c] ----------------
__global__ void attn_kernel() {
    const int bh = blockIdx.y;
    const int b  = bh >> 3;
    const int hd = bh & 7;
    const int p  = blockIdx.x * blockDim.x + threadIdx.x;
    const int h  = p >> 6;
    const int w  = p & 63;
    const int dil = (hd & 3) + 1;

    const float* qb = g_qkv + ((size_t)((b * 24 + 0 * 8 + hd) * 8)) * Pn * 4;
    const float* kb = g_qkv + ((size_t)((b * 24 + 1 * 8 + hd) * 8)) * Pn * 4;
    const float* vb = g_qkv + ((size_t)((b * 24 + 2 * 8 + hd) * 8)) * Pn * 4;

    float4 q[8];
#pragma unroll
    for (int i = 0; i < 8; i++)
        q[i] = *(const float4*)(qb + ((size_t)i * Pn + p) * 4);

    float s[9];
    int   np[9];
#pragma unroll
    for (int dy = 0; dy < 3; dy++) {
#pragma unroll
        for (int dx = 0; dx < 3; dx++) {
            const int j  = dy * 3 + dx;
            const int hh = h + (dy - 1) * dil;
            const int ww = w + (dx - 1) * dil;
            if (hh >= 0 && hh < Hn && ww >= 0 && ww < Wn) {
                const int pn = hh * Wn + ww;
                np[j] = pn;
                float acc = 0.f;
#pragma unroll
                for (int i = 0; i < 8; i++) {
                    float4 k4 = *(const float4*)(kb + ((size_t)i * Pn + pn) * 4);
                    acc += q[i].x * k4.x + q[i].y * k4.y + q[i].z * k4.z + q[i].w * k4.w;
                }
                s[j] = acc * SCALEF;
            } else {
                np[j] = -1;
                s[j]  = 0.f;    // zero-padded k => score 0 (still in softmax)
            }
        }
    }

    float mx = s[0];
#pragma unroll
    for (int j = 1; j < 9; j++) mx = fmaxf(mx, s[j]);
    float e[9];
    float sum = 0.f;
#pragma unroll
    for (int j = 0; j < 9; j++) { e[j] = __expf(s[j] - mx); sum += e[j]; }
    const float inv = 1.f / sum;
#pragma unroll
    for (int j = 0; j < 9; j++) e[j] *= inv;

    float ov[32];
#pragma unroll
    for (int i = 0; i < 8; i++) {
        float ox = 0.f, oy = 0.f, oz = 0.f, ow = 0.f;
#pragma unroll
        for (int j = 0; j < 9; j++) {
            if (np[j] >= 0) {
                float4 v4 = *(const float4*)(vb + ((size_t)i * Pn + np[j]) * 4);
                ox += e[j] * v4.x; oy += e[j] * v4.y;
                oz += e[j] * v4.z; ow += e[j] * v4.w;
            }
        }
        ov[i * 4 + 0] = ox; ov[i * 4 + 1] = oy; ov[i * 4 + 2] = oz; ov[i * 4 + 3] = ow;
    }

    uint32_t hw[16], lw[16];
#pragma unroll
    for (int j = 0; j < 16; j++) {
        float f0 = ov[2 * j], f1 = ov[2 * j + 1];
        __nv_bfloat162 h2 = __floats2bfloat162_rn(f0, f1);
        float r0 = f0 - __bfloat162float(h2.x);
        float r1 = f1 - __bfloat162float(h2.y);
        __nv_bfloat162 l2 = __floats2bfloat162_rn(r0, r1);
        hw[j] = *(uint32_t*)&h2;
        lw[j] = *(uint32_t*)&l2;
    }
    uint32_t* oh = (uint32_t*)(g_ahi + ((size_t)(b * Pn + p)) * 256 + hd * 32);
    uint32_t* ol = (uint32_t*)(g_alo + ((size_t)(b * Pn + p)) * 256 + hd * 32);
#pragma unroll
    for (int j = 0; j < 4; j++) {
        *(uint4*)(oh + j * 4) = make_uint4(hw[4 * j], hw[4 * j + 1], hw[4 * j + 2], hw[4 * j + 3]);
        *(uint4*)(ol + j * 4) = make_uint4(lw[4 * j], lw[4 * j + 1], lw[4 * j + 2], lw[4 * j + 3]);
    }
}

// ---------------------------------------------------------------------------
extern "C" void kernel_launch(void* const* d_in, const int* in_sizes, int n_in,
                              void* d_out, int out_size) {
    const float* x      = (const float*)d_in[0];
    const float* w_qkv  = (const float*)d_in[1];
    const float* b_qkv  = (const float*)d_in[2];
    const float* w_proj = (const float*)d_in[3];
    const float* b_proj = (const float*)d_in[4];
    float* out = (float*)d_out;

    float* qkvp = nullptr;
    __nv_bfloat16 *w1p = nullptr, *w2p = nullptr, *xhip = nullptr, *xlop = nullptr,
                  *ahip = nullptr, *alop = nullptr;
    cudaGetSymbolAddress((void**)&qkvp, g_qkv);
    cudaGetSymbolAddress((void**)&w1p, g_w1);
    cudaGetSymbolAddress((void**)&w2p, g_w2);
    cudaGetSymbolAddress((void**)&xhip, g_xhi);
    cudaGetSymbolAddress((void**)&xlop, g_xlo);
    cudaGetSymbolAddress((void**)&ahip, g_ahi);
    cudaGetSymbolAddress((void**)&alop, g_alo);

    const int SMEM_BYTES = 1024 + 98304;   // align pad + 6 x 16KB stage buffers
    cudaFuncSetAttribute(hmma_gemm<0>, cudaFuncAttributeMaxDynamicSharedMemorySize, SMEM_BYTES);
    cudaFuncSetAttribute(hmma_gemm<1>, cudaFuncAttributeMaxDynamicSharedMemorySize, SMEM_BYTES);

    prep_w<<<(768 * 768 + 256 * 768 + 255) / 256, 256>>>(w_qkv, w_proj);
    conv_split<<<dim3(Pn / 32, Cn / 32, Bn), dim3(32, 8)>>>(x, xhip, xlop);
    hmma_gemm<0><<<dim3(Pn / 128, 768 / 128, Bn), 256, SMEM_BYTES>>>(w1p, xhip, xlop, b_qkv, qkvp);
    attn_kernel<<<dim3(Pn / 128, Bn * 8), 128>>>();
    hmma_gemm<1><<<dim3(Pn / 128, 256 / 128, Bn), 256, SMEM_BYTES>>>(w2p, ahip, alop, b_proj, out);
}